// round 9
// baseline (speedup 1.0000x reference)
#include <cuda_runtime.h>
#include <cuda_bf16.h>
#include <cstdint>

// Problem constants
#define T_ 8
#define L_ 8
#define N_ 500
#define D_ 64
#define K_ 12
#define S_ 2
#define RLN (L_*N_)          // 4000
#define R_ (T_*L_*N_)        // 32000 rows of (t,l,n)
#define ELEMS (R_*D_)        // 2048000

typedef unsigned long long ull;

// ---------------- scratch buffers (no allocation allowed) ----------------
__device__ float g_dyn[ELEMS];          // all_dyn (T,L,N,D)
__device__ float g_q6[6][ELEMS];        // q, then att (in place)
__device__ float g_k6[6][ELEMS];        // k per (branch,graph)
__device__ float g_x6[6][ELEMS];        // attention output per (branch,graph)
__device__ float g_h[T_*N_];            // LSTM h_last

__device__ __forceinline__ float sigf(float x) {
    return 1.f / (1.f + __expf(-x));
}

// packed dual-fp32 FMA: acc.{lo,hi} += a.{lo,hi} * b.{lo,hi}
__device__ __forceinline__ void fma2(ull& acc, ull a, ull b) {
    asm("fma.rn.f32x2 %0, %1, %2, %0;" : "+l"(acc) : "l"(a), "l"(b));
}
__device__ __forceinline__ float lo32(ull v) { return __uint_as_float((unsigned)v); }
__device__ __forceinline__ float hi32(ull v) { return __uint_as_float((unsigned)(v >> 32)); }
__device__ __forceinline__ ull dup2(float a) {
    ull r; unsigned u = __float_as_uint(a);
    asm("mov.b64 %0, {%1, %1};" : "=l"(r) : "r"(u));
    return r;
}

// =====================================================================
// 1. evolution scan: grid 250, block 256. (R6, unchanged)
// =====================================================================
__global__ void evo_kernel(const float* __restrict__ stat,
                           const float* __restrict__ thre,
                           const float* __restrict__ dynn,
                           const float* __restrict__ w1,
                           float* __restrict__ out_nowfinal,
                           float* __restrict__ out_diffs) {
    __shared__ float w1_s[128 * 64];      // natural: w1_s[d*64+e]
    __shared__ float now_s[16][64];
    __shared__ float st_s[16][64];
    __shared__ float th_s[16];
    int tid = threadIdx.x;
    for (int i = tid; i < 8192; i += 256) w1_s[i] = w1[i];
    int e = tid & 63, grp = tid >> 6;
    int row0 = blockIdx.x * 16;
#pragma unroll
    for (int i = 0; i < 4; i++) {
        int r = grp * 4 + i;
        float v = dynn[(size_t)(row0 + r) * 64 + e];
        now_s[r][e] = v;
        g_dyn[(size_t)(row0 + r) * 64 + e] = v;   // all_dyn[t=0]
    }
    __syncthreads();

    for (int t = 1; t < T_; t++) {
        size_t base = (size_t)t * RLN + row0;
        ((float4*)st_s)[tid] = ((const float4*)(stat + base * 64))[tid];
        if (tid < 16) th_s[tid] = thre[base + tid];
        __syncthreads();

        float sum[4] = {0.f, 0.f, 0.f, 0.f};
#pragma unroll 4
        for (int d = 0; d < 64; d += 4) {
            float wn0 = w1_s[(d + 0) * 64 + e];
            float wn1 = w1_s[(d + 1) * 64 + e];
            float wn2 = w1_s[(d + 2) * 64 + e];
            float wn3 = w1_s[(d + 3) * 64 + e];
            float ws0 = w1_s[(64 + d + 0) * 64 + e];
            float ws1 = w1_s[(64 + d + 1) * 64 + e];
            float ws2 = w1_s[(64 + d + 2) * 64 + e];
            float ws3 = w1_s[(64 + d + 3) * 64 + e];
#pragma unroll
            for (int i = 0; i < 4; i++) {
                int r = grp * 4 + i;
                float4 nv = *(float4*)&now_s[r][d];
                float4 sv = *(float4*)&st_s[r][d];
                sum[i] = fmaf(nv.x, wn0, sum[i]); sum[i] = fmaf(nv.y, wn1, sum[i]);
                sum[i] = fmaf(nv.z, wn2, sum[i]); sum[i] = fmaf(nv.w, wn3, sum[i]);
                sum[i] = fmaf(sv.x, ws0, sum[i]); sum[i] = fmaf(sv.y, ws1, sum[i]);
                sum[i] = fmaf(sv.z, ws2, sum[i]); sum[i] = fmaf(sv.w, ws3, sum[i]);
            }
        }
        float vals[4];
#pragma unroll
        for (int i = 0; i < 4; i++) {
            int r = grp * 4 + i;
            float th = th_s[r];
            float nv = now_s[r][e];
            float val = sigf(sum[i] * th + nv * (1.f - th));
            vals[i] = val;
            g_dyn[(base + r) * 64 + e] = val;
            out_diffs[((size_t)(t - 1) * RLN + row0 + r) * 64 + e] = val - nv;
            if (t == T_ - 1) out_nowfinal[(size_t)(row0 + r) * 64 + e] = val;
        }
        __syncthreads();
#pragma unroll
        for (int i = 0; i < 4; i++) now_s[grp * 4 + i][e] = vals[i];
        __syncthreads();
    }
}

// =====================================================================
// 2. pass1 (R4/R6 exact, measured 93.4us): q/k GEMM, f32x2 col-pairs,
//    natural W, reg-dup'd A. grid 3000 (6 bg x 500), block 256.
// =====================================================================
#define AT_PITCH 68
#define ANAT_PITCH 65
#define W_PITCH 132
#define P1_SMEM ((64*AT_PITCH + 64*W_PITCH) * 4)    // 51200

__global__ void __launch_bounds__(256)
pass1_kernel(const float* __restrict__ stat,
             const float* __restrict__ wq_all,
             const float* __restrict__ wk_all,
             int s) {
    extern __shared__ float sm[];
    float* At = sm;                      // [64][AT_PITCH]
    float* W_s = sm + 64 * AT_PITCH;     // [64][W_PITCH]
    float* A_nat = W_s;                  // transient staging [64][ANAT_PITCH]
    int tid = threadIdx.x;
    int bg = blockIdx.x / 500;
    int blk = blockIdx.x - bg * 500;

    const float* src;
    if (s == 0) src = (bg < 3) ? (const float*)g_dyn : stat;
    else        src = g_x6[bg];
    const float* x = src + (size_t)blk * 64 * 64;

    for (int i = tid; i < 4096; i += 256) {
        int row = i >> 6, k = i & 63;
        A_nat[row * ANAT_PITCH + k] = x[i];
    }
    __syncthreads();
    {
        int k = tid & 63, rg = tid >> 6;
#pragma unroll
        for (int r16 = 0; r16 < 16; r16++) {
            int row = rg * 16 + r16;
            At[k * AT_PITCH + row] = A_nat[row * ANAT_PITCH + k];
        }
    }
    __syncthreads();
    {
        const float4* wq4 = (const float4*)(wq_all + (size_t)(bg * 2 + s) * 4096);
        const float4* wk4 = (const float4*)(wk_all + (size_t)(bg * 2 + s) * 4096);
        for (int i = tid; i < 2048; i += 256) {
            int half = i >> 10, idx = i & 1023;
            int k = idx >> 4, c4 = (idx & 15) << 2;
            float4 v = half ? wk4[idx] : wq4[idx];
            *(float4*)&W_s[k * W_PITCH + half * 64 + c4] = v;
        }
    }
    __syncthreads();

    int tx = tid & 31, ty = tid >> 5;
    ull acc[8][2];
#pragma unroll
    for (int r = 0; r < 8; r++) { acc[r][0] = 0ull; acc[r][1] = 0ull; }

#pragma unroll 4
    for (int k = 0; k < 64; k++) {
        float4 a0 = *(const float4*)&At[k * AT_PITCH + ty * 8];
        float4 a1 = *(const float4*)&At[k * AT_PITCH + ty * 8 + 4];
        const ull* wrow = (const ull*)&W_s[k * W_PITCH];
        ull wq2 = wrow[tx];
        ull wk2 = wrow[tx + 32];
        ull ad[8];
        ad[0] = dup2(a0.x); ad[1] = dup2(a0.y); ad[2] = dup2(a0.z); ad[3] = dup2(a0.w);
        ad[4] = dup2(a1.x); ad[5] = dup2(a1.y); ad[6] = dup2(a1.z); ad[7] = dup2(a1.w);
#pragma unroll
        for (int r = 0; r < 8; r++) {
            fma2(acc[r][0], ad[r], wq2);
            fma2(acc[r][1], ad[r], wk2);
        }
    }

    float* qdst = g_q6[bg];
    float* kdst = g_k6[bg];
    size_t rowbase = (size_t)blk * 64 + ty * 8;
#pragma unroll
    for (int r = 0; r < 8; r++) {
        size_t ro = (rowbase + r) * 64 + 2 * tx;
        *(float2*)&qdst[ro] = make_float2(lo32(acc[r][0]), hi32(acc[r][0]));
        *(float2*)&kdst[ro] = make_float2(lo32(acc[r][1]), hi32(acc[r][1]));
    }
}

// =====================================================================
// 3. pass2a: gather + softmax + weighted sum ONLY. (R8, unchanged)
//    att = q + sum a*k written IN PLACE into g_q6.
// =====================================================================
#define KS_FLOATS (N_ * 64)                     // 32000 floats = 128000 B
#define P2A_SMEM (KS_FLOATS * 4)

__global__ void __launch_bounds__(512)
pass2a_kernel(const int* __restrict__ n0,
              const int* __restrict__ n1,
              const int* __restrict__ n2) {
    extern __shared__ float smf[];
    float* k_s = smf;                           // [500][64] natural
    int tid = threadIdx.x;
    int bg = blockIdx.x / 64;
    int tl = blockIdx.x - bg * 64;
    int gi3 = bg % 3;
    const int* neigh = (gi3 == 0) ? n0 : (gi3 == 1) ? n1 : n2;

    float* qb = g_q6[bg] + (size_t)tl * N_ * 64;      // read q, write att
    const float* kb = g_k6[bg] + (size_t)tl * N_ * 64;

    {
        const float4* kb4 = (const float4*)kb;
        float4* ks4 = (float4*)k_s;
        for (int i = tid; i < 8000; i += 512) ks4[i] = kb4[i];
    }
    __syncthreads();

    int w = tid >> 5, lane = tid & 31;
    int half = lane >> 4, l16 = lane & 15;

    for (int it = 0; it < 8; it++) {
        int rw0 = it * 64 + w * 4;
        if (rw0 < N_) {
#pragma unroll
            for (int pr = 0; pr < 2; pr++) {
                int n = rw0 + pr * 2 + half;
                float4 q = *(const float4*)&qb[(size_t)n * 64 + l16 * 4];
                float dots[K_];
                float4 kv[K_];
#pragma unroll
                for (int j = 0; j < K_; j++) {
                    int nb = __ldg(&neigh[n * K_ + j]);
                    kv[j] = *(const float4*)&k_s[nb * 64 + l16 * 4];
                    float d = q.x * kv[j].x + q.y * kv[j].y + q.z * kv[j].z + q.w * kv[j].w;
                    d += __shfl_xor_sync(0xffffffffu, d, 8);
                    d += __shfl_xor_sync(0xffffffffu, d, 4);
                    d += __shfl_xor_sync(0xffffffffu, d, 2);
                    d += __shfl_xor_sync(0xffffffffu, d, 1);
                    dots[j] = d;
                }
                float m = dots[0];
#pragma unroll
                for (int j = 1; j < K_; j++) m = fmaxf(m, dots[j]);
                float ssum = 0.f;
#pragma unroll
                for (int j = 0; j < K_; j++) {
                    dots[j] = __expf(dots[j] - m);
                    ssum += dots[j];
                }
                float inv = 1.f / ssum;
                float4 o = q;
#pragma unroll
                for (int j = 0; j < K_; j++) {
                    float a = dots[j] * inv;
                    o.x = fmaf(a, kv[j].x, o.x);
                    o.y = fmaf(a, kv[j].y, o.y);
                    o.z = fmaf(a, kv[j].z, o.z);
                    o.w = fmaf(a, kv[j].w, o.w);
                }
                *(float4*)&qb[(size_t)n * 64 + l16 * 4] = o;   // att in place
            }
        }
    }
}

// =====================================================================
// 4. pass2b v2: x = sigmoid(att @ wd). grid 3000, block 256.
//    ROW-PAIR f32x2 with wd DUPLICATED IN SMEM -> zero dup2 in loop.
//    per k: 2 broadcast LDS.128 (A row-pairs) + 2 LDS.64 (dup'd wd) + 8 fma2.
// =====================================================================
#define P2B_AT 68
#define P2B_WD2_OFF (64 * P2B_AT * 4)              // byte offset of Wd2
#define P2B_SMEM (P2B_WD2_OFF + 64 * 64 * 8)       // 17408 + 32768 = 50176

__global__ void __launch_bounds__(256)
pass2b_kernel(const float* __restrict__ wd_all, int s) {
    extern __shared__ char smc2[];
    float* At = (float*)smc2;                      // [64][68] transposed att
    ull* Wd2 = (ull*)(smc2 + P2B_WD2_OFF);         // [64][64] dup'd wd
    float* A_nat = (float*)Wd2;                    // transient [64][65] (16640 B)
    int tid = threadIdx.x;
    int bg = blockIdx.x / 500;
    int blk = blockIdx.x - bg * 500;

    const float* att = g_q6[bg] + (size_t)blk * 4096;
    // phase 1: coalesced load att -> A_nat (pitch 65)
    for (int i = tid; i < 4096; i += 256) {
        int row = i >> 6, k = i & 63;
        A_nat[row * 65 + k] = att[i];
    }
    __syncthreads();
    // phase 2: transpose into At[k][row]
    for (int i = tid; i < 4096; i += 256) {
        int k = i >> 6, row = i & 63;
        At[k * P2B_AT + row] = A_nat[row * 65 + k];
    }
    __syncthreads();
    // phase 3: wd duplicated into Wd2 (overwrites A_nat region)
    {
        const float* wd = wd_all + (size_t)(bg * 2 + s) * 4096;
        for (int i = tid; i < 4096; i += 256) Wd2[i] = dup2(wd[i]);
    }
    __syncthreads();

    int tx = tid & 31, ty = tid >> 5;   // warp owns rows ty*8..+7 (4 pairs)
    ull acc[4][2];
#pragma unroll
    for (int p = 0; p < 4; p++) { acc[p][0] = 0ull; acc[p][1] = 0ull; }

#pragma unroll 4
    for (int k = 0; k < 64; k++) {
        const ulonglong2* ar = (const ulonglong2*)(At + k * P2B_AT + ty * 8);
        ulonglong2 a01 = ar[0];           // {rows 0,1},{rows 2,3} of group
        ulonglong2 a23 = ar[1];           // {rows 4,5},{rows 6,7}
        const ull* wrow = Wd2 + k * 64;
        ull w0 = wrow[tx];                // col tx dup'd
        ull w1 = wrow[tx + 32];           // col tx+32 dup'd
        fma2(acc[0][0], a01.x, w0); fma2(acc[0][1], a01.x, w1);
        fma2(acc[1][0], a01.y, w0); fma2(acc[1][1], a01.y, w1);
        fma2(acc[2][0], a23.x, w0); fma2(acc[2][1], a23.x, w1);
        fma2(acc[3][0], a23.y, w0); fma2(acc[3][1], a23.y, w1);
    }

    float* xdst = g_x6[bg] + (size_t)blk * 4096;
#pragma unroll
    for (int p = 0; p < 4; p++) {
        int r0 = ty * 8 + 2 * p;
        xdst[(size_t)r0 * 64 + tx]            = sigf(lo32(acc[p][0]));
        xdst[(size_t)(r0 + 1) * 64 + tx]      = sigf(hi32(acc[p][0]));
        xdst[(size_t)r0 * 64 + tx + 32]       = sigf(lo32(acc[p][1]));
        xdst[(size_t)(r0 + 1) * 64 + tx + 32] = sigf(hi32(acc[p][1]));
    }
}

// =====================================================================
// 5. LSTM over L with FUSED mix: warp per (t,n). grid 500 x 256. (R7)
// =====================================================================
__global__ void lstm_kernel(const float* __restrict__ convw,
                            const float* __restrict__ convb,
                            const float* __restrict__ wmix) {
    __shared__ float cw[4 * 129];
    __shared__ float cb[4];
    __shared__ float wm_s[2 * 192];
    int tid = threadIdx.x;
    for (int i = tid; i < 516; i += 256) cw[i] = convw[i];
    if (tid < 4) cb[tid] = convb[tid];
    if (tid < 128) {
        wm_s[tid] = wmix[tid];
        wm_s[tid + 128] = wmix[tid + 128];
        wm_s[tid + 256] = wmix[tid + 256];
    }
    __syncthreads();
    int gw = blockIdx.x * 8 + (tid >> 5);
    int lane = tid & 31;
    int t = gw / N_, n = gw % N_;
    int b = lane >> 4;
    int dl = (lane & 15) * 4;
    int dbase = b * 64 + dl;
    float wreg[4][4], wh[4], bb[4];
#pragma unroll
    for (int i = 0; i < 4; i++) {
#pragma unroll
        for (int q = 0; q < 4; q++) wreg[i][q] = cw[i * 129 + dbase + q];
        wh[i] = cw[i * 129 + 128];
        bb[i] = cb[i];
    }
    const float* wm = wm_s + b * 192;
    float4 m0 = *(const float4*)&wm[dl];
    float4 m1 = *(const float4*)&wm[64 + dl];
    float4 m2 = *(const float4*)&wm[128 + dl];

    float h = 0.f, c = 0.f;
    for (int l = 0; l < L_; l++) {
        size_t off = (((size_t)t * L_ + l) * N_ + n) * 64 + dl;
        float4 x0 = *(const float4*)&g_x6[b * 3 + 0][off];
        float4 x1 = *(const float4*)&g_x6[b * 3 + 1][off];
        float4 x2 = *(const float4*)&g_x6[b * 3 + 2][off];
        float4 xin;
        xin.x = sigf(x0.x * m0.x + x1.x * m1.x + x2.x * m2.x);
        xin.y = sigf(x0.y * m0.y + x1.y * m1.y + x2.y * m2.y);
        xin.z = sigf(x0.z * m0.z + x1.z * m1.z + x2.z * m2.z);
        xin.w = sigf(x0.w * m0.w + x1.w * m1.w + x2.w * m2.w);
        float s[4];
#pragma unroll
        for (int i = 0; i < 4; i++) {
            s[i] = xin.x * wreg[i][0] + xin.y * wreg[i][1] +
                   xin.z * wreg[i][2] + xin.w * wreg[i][3];
#pragma unroll
            for (int o = 16; o; o >>= 1)
                s[i] += __shfl_xor_sync(0xffffffffu, s[i], o);
        }
        float gi = sigf(s[0] + h * wh[0] + bb[0]);
        float gf = sigf(s[1] + h * wh[1] + bb[1]);
        float go = sigf(s[2] + h * wh[2] + bb[2]);
        float gg = tanhf(s[3] + h * wh[3] + bb[3]);
        c = gf * c + gi * gg;
        h = go * tanhf(c);
    }
    if (lane == 0) g_h[t * N_ + n] = h;
}

// =====================================================================
// 6. final projection: grid T_, block 512
// =====================================================================
__global__ void final_kernel(const float* __restrict__ finw,
                             const float* __restrict__ finb,
                             float* __restrict__ out) {
    __shared__ float hs[500];
    int t = blockIdx.x, tid = threadIdx.x;
    if (tid < 500) hs[tid] = g_h[t * N_ + tid];
    __syncthreads();
    if (tid < 500) {
        float acc = finb[tid];
        const float4* wr = (const float4*)(finw + (size_t)tid * 500);
#pragma unroll 5
        for (int m4 = 0; m4 < 125; m4++) {
            float4 wv = wr[m4];
            acc = fmaf(hs[m4 * 4 + 0], wv.x, acc);
            acc = fmaf(hs[m4 * 4 + 1], wv.y, acc);
            acc = fmaf(hs[m4 * 4 + 2], wv.z, acc);
            acc = fmaf(hs[m4 * 4 + 3], wv.w, acc);
        }
        out[t * N_ + tid] = sigf(acc);
    }
}

// ---------------- launcher ----------------
extern "C" void kernel_launch(void* const* d_in, const int* in_sizes, int n_in,
                              void* d_out, int out_size) {
    const float* stat = (const float*)d_in[0];
    const float* thre = (const float*)d_in[1];
    const float* dynn = (const float*)d_in[2];
    const int* npoi = (const int*)d_in[3];
    const int* nroad = (const int*)d_in[4];
    const int* nrec = (const int*)d_in[5];
    const float* w1 = (const float*)d_in[6];
    const float* wq = (const float*)d_in[7];
    const float* wk = (const float*)d_in[8];
    const float* wdm = (const float*)d_in[9];
    const float* wmix = (const float*)d_in[10];
    const float* convw = (const float*)d_in[11];
    const float* convb = (const float*)d_in[12];
    const float* finw = (const float*)d_in[13];
    const float* finb = (const float*)d_in[14];

    float* out = (float*)d_out;
    float* out_scores = out;                          // (T,N)       4000
    float* out_nowfinal = out + T_ * N_;              // (L,N,D)     256000
    float* out_diffs = out + T_ * N_ + L_ * N_ * D_;  // (T-1,L,N,D) 1792000

    cudaFuncSetAttribute(pass1_kernel,
                         cudaFuncAttributeMaxDynamicSharedMemorySize, P1_SMEM);
    cudaFuncSetAttribute(pass2a_kernel,
                         cudaFuncAttributeMaxDynamicSharedMemorySize, P2A_SMEM);
    cudaFuncSetAttribute(pass2b_kernel,
                         cudaFuncAttributeMaxDynamicSharedMemorySize, P2B_SMEM);

    evo_kernel<<<250, 256>>>(stat, thre, dynn, w1, out_nowfinal, out_diffs);

    for (int s = 0; s < S_; s++) {
        pass1_kernel<<<3000, 256, P1_SMEM>>>(stat, wq, wk, s);
        pass2a_kernel<<<384, 512, P2A_SMEM>>>(npoi, nroad, nrec);
        pass2b_kernel<<<3000, 256, P2B_SMEM>>>(wdm, s);
    }

    lstm_kernel<<<500, 256>>>(convw, convb, wmix);
    final_kernel<<<T_, 512>>>(finw, finb, out_scores);
}

// round 10
// speedup vs baseline: 1.1484x; 1.1484x over previous
#include <cuda_runtime.h>
#include <cuda_bf16.h>
#include <cstdint>

// Problem constants
#define T_ 8
#define L_ 8
#define N_ 500
#define D_ 64
#define K_ 12
#define S_ 2
#define RLN (L_*N_)          // 4000
#define R_ (T_*L_*N_)        // 32000 rows of (t,l,n)
#define ELEMS (R_*D_)        // 2048000

typedef unsigned long long ull;

// ---------------- scratch buffers (no allocation allowed) ----------------
__device__ float g_dyn[ELEMS];          // all_dyn (T,L,N,D)
__device__ float g_q6[6][ELEMS];        // q, then att (in place)
__device__ float g_k6[6][ELEMS];        // k per (branch,graph)
__device__ float g_x6[6][ELEMS];        // attention output per (branch,graph)
__device__ float g_h[T_*N_];            // LSTM h_last

__device__ __forceinline__ float sigf(float x) {
    return 1.f / (1.f + __expf(-x));
}

// packed dual-fp32 FMA: acc.{lo,hi} += a.{lo,hi} * b.{lo,hi}
__device__ __forceinline__ void fma2(ull& acc, ull a, ull b) {
    asm("fma.rn.f32x2 %0, %1, %2, %0;" : "+l"(acc) : "l"(a), "l"(b));
}
__device__ __forceinline__ float lo32(ull v) { return __uint_as_float((unsigned)v); }
__device__ __forceinline__ float hi32(ull v) { return __uint_as_float((unsigned)(v >> 32)); }
__device__ __forceinline__ ull dup2(float a) {
    ull r; unsigned u = __float_as_uint(a);
    asm("mov.b64 %0, {%1, %1};" : "=l"(r) : "r"(u));
    return r;
}

// =====================================================================
// 1. evolution scan: grid 250, block 256. (R6, unchanged)
// =====================================================================
__global__ void evo_kernel(const float* __restrict__ stat,
                           const float* __restrict__ thre,
                           const float* __restrict__ dynn,
                           const float* __restrict__ w1,
                           float* __restrict__ out_nowfinal,
                           float* __restrict__ out_diffs) {
    __shared__ float w1_s[128 * 64];      // natural: w1_s[d*64+e]
    __shared__ float now_s[16][64];
    __shared__ float st_s[16][64];
    __shared__ float th_s[16];
    int tid = threadIdx.x;
    for (int i = tid; i < 8192; i += 256) w1_s[i] = w1[i];
    int e = tid & 63, grp = tid >> 6;
    int row0 = blockIdx.x * 16;
#pragma unroll
    for (int i = 0; i < 4; i++) {
        int r = grp * 4 + i;
        float v = dynn[(size_t)(row0 + r) * 64 + e];
        now_s[r][e] = v;
        g_dyn[(size_t)(row0 + r) * 64 + e] = v;   // all_dyn[t=0]
    }
    __syncthreads();

    for (int t = 1; t < T_; t++) {
        size_t base = (size_t)t * RLN + row0;
        ((float4*)st_s)[tid] = ((const float4*)(stat + base * 64))[tid];
        if (tid < 16) th_s[tid] = thre[base + tid];
        __syncthreads();

        float sum[4] = {0.f, 0.f, 0.f, 0.f};
#pragma unroll 4
        for (int d = 0; d < 64; d += 4) {
            float wn0 = w1_s[(d + 0) * 64 + e];
            float wn1 = w1_s[(d + 1) * 64 + e];
            float wn2 = w1_s[(d + 2) * 64 + e];
            float wn3 = w1_s[(d + 3) * 64 + e];
            float ws0 = w1_s[(64 + d + 0) * 64 + e];
            float ws1 = w1_s[(64 + d + 1) * 64 + e];
            float ws2 = w1_s[(64 + d + 2) * 64 + e];
            float ws3 = w1_s[(64 + d + 3) * 64 + e];
#pragma unroll
            for (int i = 0; i < 4; i++) {
                int r = grp * 4 + i;
                float4 nv = *(float4*)&now_s[r][d];
                float4 sv = *(float4*)&st_s[r][d];
                sum[i] = fmaf(nv.x, wn0, sum[i]); sum[i] = fmaf(nv.y, wn1, sum[i]);
                sum[i] = fmaf(nv.z, wn2, sum[i]); sum[i] = fmaf(nv.w, wn3, sum[i]);
                sum[i] = fmaf(sv.x, ws0, sum[i]); sum[i] = fmaf(sv.y, ws1, sum[i]);
                sum[i] = fmaf(sv.z, ws2, sum[i]); sum[i] = fmaf(sv.w, ws3, sum[i]);
            }
        }
        float vals[4];
#pragma unroll
        for (int i = 0; i < 4; i++) {
            int r = grp * 4 + i;
            float th = th_s[r];
            float nv = now_s[r][e];
            float val = sigf(sum[i] * th + nv * (1.f - th));
            vals[i] = val;
            g_dyn[(base + r) * 64 + e] = val;
            out_diffs[((size_t)(t - 1) * RLN + row0 + r) * 64 + e] = val - nv;
            if (t == T_ - 1) out_nowfinal[(size_t)(row0 + r) * 64 + e] = val;
        }
        __syncthreads();
#pragma unroll
        for (int i = 0; i < 4; i++) now_s[grp * 4 + i][e] = vals[i];
        __syncthreads();
    }
}

// =====================================================================
// 2. pass1 (R4/R6 exact): q/k GEMM, f32x2 col-pairs, natural W,
//    reg-dup'd A. grid 3000 (6 bg x 500), block 256. s=0 only now.
// =====================================================================
#define AT_PITCH 68
#define ANAT_PITCH 65
#define W_PITCH 132
#define P1_SMEM ((64*AT_PITCH + 64*W_PITCH) * 4)    // 51200

__global__ void __launch_bounds__(256)
pass1_kernel(const float* __restrict__ stat,
             const float* __restrict__ wq_all,
             const float* __restrict__ wk_all) {
    extern __shared__ float sm[];
    float* At = sm;                      // [64][AT_PITCH]
    float* W_s = sm + 64 * AT_PITCH;     // [64][W_PITCH]
    float* A_nat = W_s;                  // transient staging [64][ANAT_PITCH]
    int tid = threadIdx.x;
    int bg = blockIdx.x / 500;
    int blk = blockIdx.x - bg * 500;

    const float* src = (bg < 3) ? (const float*)g_dyn : stat;
    const float* x = src + (size_t)blk * 64 * 64;

    for (int i = tid; i < 4096; i += 256) {
        int row = i >> 6, k = i & 63;
        A_nat[row * ANAT_PITCH + k] = x[i];
    }
    __syncthreads();
    {
        int k = tid & 63, rg = tid >> 6;
#pragma unroll
        for (int r16 = 0; r16 < 16; r16++) {
            int row = rg * 16 + r16;
            At[k * AT_PITCH + row] = A_nat[row * ANAT_PITCH + k];
        }
    }
    __syncthreads();
    {
        const float4* wq4 = (const float4*)(wq_all + (size_t)(bg * 2) * 4096);
        const float4* wk4 = (const float4*)(wk_all + (size_t)(bg * 2) * 4096);
        for (int i = tid; i < 2048; i += 256) {
            int half = i >> 10, idx = i & 1023;
            int k = idx >> 4, c4 = (idx & 15) << 2;
            float4 v = half ? wk4[idx] : wq4[idx];
            *(float4*)&W_s[k * W_PITCH + half * 64 + c4] = v;
        }
    }
    __syncthreads();

    int tx = tid & 31, ty = tid >> 5;
    ull acc[8][2];
#pragma unroll
    for (int r = 0; r < 8; r++) { acc[r][0] = 0ull; acc[r][1] = 0ull; }

#pragma unroll 4
    for (int k = 0; k < 64; k++) {
        float4 a0 = *(const float4*)&At[k * AT_PITCH + ty * 8];
        float4 a1 = *(const float4*)&At[k * AT_PITCH + ty * 8 + 4];
        const ull* wrow = (const ull*)&W_s[k * W_PITCH];
        ull wq2 = wrow[tx];
        ull wk2 = wrow[tx + 32];
        ull ad[8];
        ad[0] = dup2(a0.x); ad[1] = dup2(a0.y); ad[2] = dup2(a0.z); ad[3] = dup2(a0.w);
        ad[4] = dup2(a1.x); ad[5] = dup2(a1.y); ad[6] = dup2(a1.z); ad[7] = dup2(a1.w);
#pragma unroll
        for (int r = 0; r < 8; r++) {
            fma2(acc[r][0], ad[r], wq2);
            fma2(acc[r][1], ad[r], wk2);
        }
    }

    float* qdst = g_q6[bg];
    float* kdst = g_k6[bg];
    size_t rowbase = (size_t)blk * 64 + ty * 8;
#pragma unroll
    for (int r = 0; r < 8; r++) {
        size_t ro = (rowbase + r) * 64 + 2 * tx;
        *(float2*)&qdst[ro] = make_float2(lo32(acc[r][0]), hi32(acc[r][0]));
        *(float2*)&kdst[ro] = make_float2(lo32(acc[r][1]), hi32(acc[r][1]));
    }
}

// =====================================================================
// 3. pass2a: gather + softmax + weighted sum ONLY. (R8, unchanged)
//    att = q + sum a*k written IN PLACE into g_q6.
// =====================================================================
#define KS_FLOATS (N_ * 64)                     // 32000 floats = 128000 B
#define P2A_SMEM (KS_FLOATS * 4)

__global__ void __launch_bounds__(512)
pass2a_kernel(const int* __restrict__ n0,
              const int* __restrict__ n1,
              const int* __restrict__ n2) {
    extern __shared__ float smf[];
    float* k_s = smf;                           // [500][64] natural
    int tid = threadIdx.x;
    int bg = blockIdx.x / 64;
    int tl = blockIdx.x - bg * 64;
    int gi3 = bg % 3;
    const int* neigh = (gi3 == 0) ? n0 : (gi3 == 1) ? n1 : n2;

    float* qb = g_q6[bg] + (size_t)tl * N_ * 64;      // read q, write att
    const float* kb = g_k6[bg] + (size_t)tl * N_ * 64;

    {
        const float4* kb4 = (const float4*)kb;
        float4* ks4 = (float4*)k_s;
        for (int i = tid; i < 8000; i += 512) ks4[i] = kb4[i];
    }
    __syncthreads();

    int w = tid >> 5, lane = tid & 31;
    int half = lane >> 4, l16 = lane & 15;

    for (int it = 0; it < 8; it++) {
        int rw0 = it * 64 + w * 4;
        if (rw0 < N_) {
#pragma unroll
            for (int pr = 0; pr < 2; pr++) {
                int n = rw0 + pr * 2 + half;
                float4 q = *(const float4*)&qb[(size_t)n * 64 + l16 * 4];
                float dots[K_];
                float4 kv[K_];
#pragma unroll
                for (int j = 0; j < K_; j++) {
                    int nb = __ldg(&neigh[n * K_ + j]);
                    kv[j] = *(const float4*)&k_s[nb * 64 + l16 * 4];
                    float d = q.x * kv[j].x + q.y * kv[j].y + q.z * kv[j].z + q.w * kv[j].w;
                    d += __shfl_xor_sync(0xffffffffu, d, 8);
                    d += __shfl_xor_sync(0xffffffffu, d, 4);
                    d += __shfl_xor_sync(0xffffffffu, d, 2);
                    d += __shfl_xor_sync(0xffffffffu, d, 1);
                    dots[j] = d;
                }
                float m = dots[0];
#pragma unroll
                for (int j = 1; j < K_; j++) m = fmaxf(m, dots[j]);
                float ssum = 0.f;
#pragma unroll
                for (int j = 0; j < K_; j++) {
                    dots[j] = __expf(dots[j] - m);
                    ssum += dots[j];
                }
                float inv = 1.f / ssum;
                float4 o = q;
#pragma unroll
                for (int j = 0; j < K_; j++) {
                    float a = dots[j] * inv;
                    o.x = fmaf(a, kv[j].x, o.x);
                    o.y = fmaf(a, kv[j].y, o.y);
                    o.z = fmaf(a, kv[j].z, o.z);
                    o.w = fmaf(a, kv[j].w, o.w);
                }
                *(float4*)&qb[(size_t)n * 64 + l16 * 4] = o;   // att in place
            }
        }
    }
}

// =====================================================================
// 4. FUSED pass2b(s=0) + pass1(s=1): grid 3000, block 256.
//    x = sigmoid(att@wd0) computed into smem (never hits gmem), then
//    q/k = x@wq1|wk1 written to g_q6/g_k6. smem = 51200 (same as pass1).
// =====================================================================
__global__ void __launch_bounds__(256)
fused_kernel(const float* __restrict__ wd_all,
             const float* __restrict__ wq_all,
             const float* __restrict__ wk_all) {
    extern __shared__ float smF[];
    float* At = smF;                        // [64][68]
    float* W_s = smF + 64 * AT_PITCH;       // [64][132]
    float* A_nat = W_s;                     // [64][65] transient (4160 floats)
    float* wd_s = W_s + 4160;               // [64][64] natural (4096 floats)
    int tid = threadIdx.x;
    int bg = blockIdx.x / 500;
    int blk = blockIdx.x - bg * 500;

    const float* att = g_q6[bg] + (size_t)blk * 4096;
    // phase 1: att -> A_nat (pitch 65); wd(s=0) -> wd_s
    for (int i = tid; i < 4096; i += 256) {
        int row = i >> 6, k = i & 63;
        A_nat[row * 65 + k] = att[i];
    }
    {
        const float4* wd4 = (const float4*)(wd_all + (size_t)(bg * 2) * 4096);
        for (int i = tid; i < 1024; i += 256) ((float4*)wd_s)[i] = wd4[i];
    }
    __syncthreads();
    // phase 2: transpose att -> At
    for (int i = tid; i < 4096; i += 256) {
        int k = i >> 6, row = i & 63;
        At[k * AT_PITCH + row] = A_nat[row * 65 + k];
    }
    __syncthreads();

    int tx = tid & 31, ty = tid >> 5;
    // phase 3: x-GEMM (R8 v1 loop): att@wd, row-pair f32x2, reg-dup'd wd
    ull accx[4][2];
#pragma unroll
    for (int p = 0; p < 4; p++) { accx[p][0] = 0ull; accx[p][1] = 0ull; }
#pragma unroll 4
    for (int k = 0; k < 64; k++) {
        const ulonglong2* ar = (const ulonglong2*)(At + k * AT_PITCH + ty * 8);
        ulonglong2 a01 = ar[0];
        ulonglong2 a23 = ar[1];
        ull w0 = dup2(wd_s[k * 64 + tx]);
        ull w1 = dup2(wd_s[k * 64 + tx + 32]);
        fma2(accx[0][0], a01.x, w0); fma2(accx[0][1], a01.x, w1);
        fma2(accx[1][0], a01.y, w0); fma2(accx[1][1], a01.y, w1);
        fma2(accx[2][0], a23.x, w0); fma2(accx[2][1], a23.x, w1);
        fma2(accx[3][0], a23.y, w0); fma2(accx[3][1], a23.y, w1);
    }
    __syncthreads();   // everyone done reading At + wd_s

    // phase 4: store xT directly into At [col][row]; load wq/wk(s=1) into W_s
#pragma unroll
    for (int p = 0; p < 4; p++) {
        int r0 = ty * 8 + 2 * p;
        *(float2*)&At[tx * AT_PITCH + r0] =
            make_float2(sigf(lo32(accx[p][0])), sigf(hi32(accx[p][0])));
        *(float2*)&At[(tx + 32) * AT_PITCH + r0] =
            make_float2(sigf(lo32(accx[p][1])), sigf(hi32(accx[p][1])));
    }
    {
        const float4* wq4 = (const float4*)(wq_all + (size_t)(bg * 2 + 1) * 4096);
        const float4* wk4 = (const float4*)(wk_all + (size_t)(bg * 2 + 1) * 4096);
        for (int i = tid; i < 2048; i += 256) {
            int half = i >> 10, idx = i & 1023;
            int k = idx >> 4, c4 = (idx & 15) << 2;
            float4 v = half ? wk4[idx] : wq4[idx];
            *(float4*)&W_s[k * W_PITCH + half * 64 + c4] = v;
        }
    }
    __syncthreads();

    // phase 5: q/k GEMM (R4 loop)
    ull acc[8][2];
#pragma unroll
    for (int r = 0; r < 8; r++) { acc[r][0] = 0ull; acc[r][1] = 0ull; }
#pragma unroll 4
    for (int k = 0; k < 64; k++) {
        float4 a0 = *(const float4*)&At[k * AT_PITCH + ty * 8];
        float4 a1 = *(const float4*)&At[k * AT_PITCH + ty * 8 + 4];
        const ull* wrow = (const ull*)&W_s[k * W_PITCH];
        ull wq2 = wrow[tx];
        ull wk2 = wrow[tx + 32];
        ull ad[8];
        ad[0] = dup2(a0.x); ad[1] = dup2(a0.y); ad[2] = dup2(a0.z); ad[3] = dup2(a0.w);
        ad[4] = dup2(a1.x); ad[5] = dup2(a1.y); ad[6] = dup2(a1.z); ad[7] = dup2(a1.w);
#pragma unroll
        for (int r = 0; r < 8; r++) {
            fma2(acc[r][0], ad[r], wq2);
            fma2(acc[r][1], ad[r], wk2);
        }
    }

    float* qdst = g_q6[bg];
    float* kdst = g_k6[bg];
    size_t rowbase = (size_t)blk * 64 + ty * 8;
#pragma unroll
    for (int r = 0; r < 8; r++) {
        size_t ro = (rowbase + r) * 64 + 2 * tx;
        *(float2*)&qdst[ro] = make_float2(lo32(acc[r][0]), hi32(acc[r][0]));
        *(float2*)&kdst[ro] = make_float2(lo32(acc[r][1]), hi32(acc[r][1]));
    }
}

// =====================================================================
// 5. pass2b (R8 v1 exact, measured 70.6us): x = sigmoid(att @ wd).
//    grid 3000, block 256. s=1 only now.
// =====================================================================
#define P2B_AT 68
#define P2B_AUX_OFF (64 * P2B_AT)                 // floats
#define P2B_SMEM ((64 * P2B_AT + 64 * 65) * 4)    // 34048

__global__ void __launch_bounds__(256)
pass2b_kernel(const float* __restrict__ wd_all) {
    extern __shared__ float sm2[];
    float* At = sm2;                    // [64][68] transposed att
    float* aux = sm2 + P2B_AUX_OFF;     // x_nat [64][65], then wd [64][64]
    int tid = threadIdx.x;
    int bg = blockIdx.x / 500;
    int blk = blockIdx.x - bg * 500;

    const float* att = g_q6[bg] + (size_t)blk * 4096;
    for (int i = tid; i < 4096; i += 256) {
        int row = i >> 6, k = i & 63;
        aux[row * 65 + k] = att[i];
    }
    __syncthreads();
    for (int i = tid; i < 4096; i += 256) {
        int k = i >> 6, row = i & 63;
        At[k * P2B_AT + row] = aux[row * 65 + k];
    }
    __syncthreads();
    {
        const float4* wd4 = (const float4*)(wd_all + (size_t)(bg * 2 + 1) * 4096);
        for (int i = tid; i < 1024; i += 256) ((float4*)aux)[i] = wd4[i];
    }
    __syncthreads();

    int lane = tid & 31, ty = tid >> 5;
    ull acc[4][2];
#pragma unroll
    for (int p = 0; p < 4; p++) { acc[p][0] = 0ull; acc[p][1] = 0ull; }

#pragma unroll 4
    for (int k = 0; k < 64; k++) {
        const ulonglong2* ar = (const ulonglong2*)(At + k * P2B_AT + ty * 8);
        ulonglong2 a01 = ar[0];
        ulonglong2 a23 = ar[1];
        ull wd0 = dup2(aux[k * 64 + lane]);
        ull wd1 = dup2(aux[k * 64 + lane + 32]);
        fma2(acc[0][0], a01.x, wd0); fma2(acc[0][1], a01.x, wd1);
        fma2(acc[1][0], a01.y, wd0); fma2(acc[1][1], a01.y, wd1);
        fma2(acc[2][0], a23.x, wd0); fma2(acc[2][1], a23.x, wd1);
        fma2(acc[3][0], a23.y, wd0); fma2(acc[3][1], a23.y, wd1);
    }

    float* xdst = g_x6[bg] + (size_t)blk * 4096;
#pragma unroll
    for (int p = 0; p < 4; p++) {
        int r0 = ty * 8 + 2 * p;
        xdst[(size_t)r0 * 64 + lane]            = sigf(lo32(acc[p][0]));
        xdst[(size_t)(r0 + 1) * 64 + lane]      = sigf(hi32(acc[p][0]));
        xdst[(size_t)r0 * 64 + lane + 32]       = sigf(lo32(acc[p][1]));
        xdst[(size_t)(r0 + 1) * 64 + lane + 32] = sigf(hi32(acc[p][1]));
    }
}

// =====================================================================
// 6. LSTM over L with FUSED mix: warp per (t,n). grid 500 x 256. (R7)
// =====================================================================
__global__ void lstm_kernel(const float* __restrict__ convw,
                            const float* __restrict__ convb,
                            const float* __restrict__ wmix) {
    __shared__ float cw[4 * 129];
    __shared__ float cb[4];
    __shared__ float wm_s[2 * 192];
    int tid = threadIdx.x;
    for (int i = tid; i < 516; i += 256) cw[i] = convw[i];
    if (tid < 4) cb[tid] = convb[tid];
    if (tid < 128) {
        wm_s[tid] = wmix[tid];
        wm_s[tid + 128] = wmix[tid + 128];
        wm_s[tid + 256] = wmix[tid + 256];
    }
    __syncthreads();
    int gw = blockIdx.x * 8 + (tid >> 5);
    int lane = tid & 31;
    int t = gw / N_, n = gw % N_;
    int b = lane >> 4;
    int dl = (lane & 15) * 4;
    int dbase = b * 64 + dl;
    float wreg[4][4], wh[4], bb[4];
#pragma unroll
    for (int i = 0; i < 4; i++) {
#pragma unroll
        for (int q = 0; q < 4; q++) wreg[i][q] = cw[i * 129 + dbase + q];
        wh[i] = cw[i * 129 + 128];
        bb[i] = cb[i];
    }
    const float* wm = wm_s + b * 192;
    float4 m0 = *(const float4*)&wm[dl];
    float4 m1 = *(const float4*)&wm[64 + dl];
    float4 m2 = *(const float4*)&wm[128 + dl];

    float h = 0.f, c = 0.f;
    for (int l = 0; l < L_; l++) {
        size_t off = (((size_t)t * L_ + l) * N_ + n) * 64 + dl;
        float4 x0 = *(const float4*)&g_x6[b * 3 + 0][off];
        float4 x1 = *(const float4*)&g_x6[b * 3 + 1][off];
        float4 x2 = *(const float4*)&g_x6[b * 3 + 2][off];
        float4 xin;
        xin.x = sigf(x0.x * m0.x + x1.x * m1.x + x2.x * m2.x);
        xin.y = sigf(x0.y * m0.y + x1.y * m1.y + x2.y * m2.y);
        xin.z = sigf(x0.z * m0.z + x1.z * m1.z + x2.z * m2.z);
        xin.w = sigf(x0.w * m0.w + x1.w * m1.w + x2.w * m2.w);
        float s[4];
#pragma unroll
        for (int i = 0; i < 4; i++) {
            s[i] = xin.x * wreg[i][0] + xin.y * wreg[i][1] +
                   xin.z * wreg[i][2] + xin.w * wreg[i][3];
#pragma unroll
            for (int o = 16; o; o >>= 1)
                s[i] += __shfl_xor_sync(0xffffffffu, s[i], o);
        }
        float gi = sigf(s[0] + h * wh[0] + bb[0]);
        float gf = sigf(s[1] + h * wh[1] + bb[1]);
        float go = sigf(s[2] + h * wh[2] + bb[2]);
        float gg = tanhf(s[3] + h * wh[3] + bb[3]);
        c = gf * c + gi * gg;
        h = go * tanhf(c);
    }
    if (lane == 0) g_h[t * N_ + n] = h;
}

// =====================================================================
// 7. final projection: grid T_, block 512
// =====================================================================
__global__ void final_kernel(const float* __restrict__ finw,
                             const float* __restrict__ finb,
                             float* __restrict__ out) {
    __shared__ float hs[500];
    int t = blockIdx.x, tid = threadIdx.x;
    if (tid < 500) hs[tid] = g_h[t * N_ + tid];
    __syncthreads();
    if (tid < 500) {
        float acc = finb[tid];
        const float4* wr = (const float4*)(finw + (size_t)tid * 500);
#pragma unroll 5
        for (int m4 = 0; m4 < 125; m4++) {
            float4 wv = wr[m4];
            acc = fmaf(hs[m4 * 4 + 0], wv.x, acc);
            acc = fmaf(hs[m4 * 4 + 1], wv.y, acc);
            acc = fmaf(hs[m4 * 4 + 2], wv.z, acc);
            acc = fmaf(hs[m4 * 4 + 3], wv.w, acc);
        }
        out[t * N_ + tid] = sigf(acc);
    }
}

// ---------------- launcher ----------------
extern "C" void kernel_launch(void* const* d_in, const int* in_sizes, int n_in,
                              void* d_out, int out_size) {
    const float* stat = (const float*)d_in[0];
    const float* thre = (const float*)d_in[1];
    const float* dynn = (const float*)d_in[2];
    const int* npoi = (const int*)d_in[3];
    const int* nroad = (const int*)d_in[4];
    const int* nrec = (const int*)d_in[5];
    const float* w1 = (const float*)d_in[6];
    const float* wq = (const float*)d_in[7];
    const float* wk = (const float*)d_in[8];
    const float* wdm = (const float*)d_in[9];
    const float* wmix = (const float*)d_in[10];
    const float* convw = (const float*)d_in[11];
    const float* convb = (const float*)d_in[12];
    const float* finw = (const float*)d_in[13];
    const float* finb = (const float*)d_in[14];

    float* out = (float*)d_out;
    float* out_scores = out;                          // (T,N)       4000
    float* out_nowfinal = out + T_ * N_;              // (L,N,D)     256000
    float* out_diffs = out + T_ * N_ + L_ * N_ * D_;  // (T-1,L,N,D) 1792000

    cudaFuncSetAttribute(pass1_kernel,
                         cudaFuncAttributeMaxDynamicSharedMemorySize, P1_SMEM);
    cudaFuncSetAttribute(fused_kernel,
                         cudaFuncAttributeMaxDynamicSharedMemorySize, P1_SMEM);
    cudaFuncSetAttribute(pass2a_kernel,
                         cudaFuncAttributeMaxDynamicSharedMemorySize, P2A_SMEM);
    cudaFuncSetAttribute(pass2b_kernel,
                         cudaFuncAttributeMaxDynamicSharedMemorySize, P2B_SMEM);

    evo_kernel<<<250, 256>>>(stat, thre, dynn, w1, out_nowfinal, out_diffs);

    pass1_kernel<<<3000, 256, P1_SMEM>>>(stat, wq, wk);        // s=0
    pass2a_kernel<<<384, 512, P2A_SMEM>>>(npoi, nroad, nrec);  // s=0
    fused_kernel<<<3000, 256, P1_SMEM>>>(wdm, wq, wk);         // x(s=0)+qk(s=1)
    pass2a_kernel<<<384, 512, P2A_SMEM>>>(npoi, nroad, nrec);  // s=1
    pass2b_kernel<<<3000, 256, P2B_SMEM>>>(wdm);               // s=1 -> g_x6

    lstm_kernel<<<500, 256>>>(convw, convb, wmix);
    final_kernel<<<T_, 512>>>(finw, finb, out_scores);
}